// round 9
// baseline (speedup 1.0000x reference)
#include <cuda_runtime.h>
#include <cuda_bf16.h>
#include <stdint.h>

// Problem constants
#define B_  2
#define S_  2048
#define D_  1024
#define H_  16
#define DK_ 64
#define M_  (B_ * S_)

#define QSCALE (0.125f * 1.44269504088896340736f)

// ---------------------------------------------------------------------------
// Scratch (device globals — no allocations allowed)
// ---------------------------------------------------------------------------
__device__ __nv_bfloat16 g_Ah[3][M_ * D_];   // activation hi (slot 0 reused for ctx)
__device__ __nv_bfloat16 g_Al[3][M_ * D_];   // activation lo
__device__ __nv_bfloat16 g_Wh[4][D_ * D_];   // weight hi, TRANSPOSED [N][K]
__device__ __nv_bfloat16 g_Wl[4][D_ * D_];   // weight lo

__device__ __nv_bfloat16 g_qh[B_ * H_ * S_ * DK_];  // [bh][s][dk], pre-scaled
__device__ __nv_bfloat16 g_ql[B_ * H_ * S_ * DK_];
__device__ __nv_bfloat16 g_kh[B_ * H_ * S_ * DK_];
__device__ __nv_bfloat16 g_kl[B_ * H_ * S_ * DK_];
__device__ __nv_bfloat16 g_vh[B_ * H_ * DK_ * S_];  // TRANSPOSED [bh][dk][s]
__device__ __nv_bfloat16 g_vl[B_ * H_ * DK_ * S_];

// ---------------------------------------------------------------------------
// Helpers
// ---------------------------------------------------------------------------
__device__ __forceinline__ void split1(float x, __nv_bfloat16& h, __nv_bfloat16& l) {
    h = __float2bfloat16_rn(x);
    l = __float2bfloat16_rn(x - __bfloat162float(h));
}

__device__ __forceinline__ uint32_t pack_bf16(float lo, float hi) {
    uint32_t r;
    asm("cvt.rn.bf16x2.f32 %0, %1, %2;" : "=r"(r) : "f"(hi), "f"(lo));
    return r;
}

__device__ __forceinline__ float fast_exp2(float x) {
    float r;
    asm("ex2.approx.f32 %0, %1;" : "=f"(r) : "f"(x));
    return r;
}

__device__ __forceinline__ void mma16816(float* c, const uint32_t* a, const uint32_t* b)
{
    asm("mma.sync.aligned.m16n8k16.row.col.f32.bf16.bf16.f32 "
        "{%0,%1,%2,%3},{%4,%5,%6,%7},{%8,%9},{%0,%1,%2,%3};"
        : "+f"(c[0]), "+f"(c[1]), "+f"(c[2]), "+f"(c[3])
        : "r"(a[0]), "r"(a[1]), "r"(a[2]), "r"(a[3]), "r"(b[0]), "r"(b[1]));
}

__device__ __forceinline__ void ldsm4(uint32_t* r, uint32_t addr)
{
    asm volatile("ldmatrix.sync.aligned.m8n8.x4.shared.b16 {%0,%1,%2,%3}, [%4];"
        : "=r"(r[0]), "=r"(r[1]), "=r"(r[2]), "=r"(r[3]) : "r"(addr));
}

__device__ __forceinline__ uint32_t smem_u32(const void* p) {
    return (uint32_t)__cvta_generic_to_shared(p);
}
__device__ __forceinline__ void cpa16(uint32_t d, const void* s) {
    asm volatile("cp.async.cg.shared.global [%0], [%1], 16;" :: "r"(d), "l"(s));
}
__device__ __forceinline__ void cp_commit() { asm volatile("cp.async.commit_group;"); }
__device__ __forceinline__ void cp_wait0()  { asm volatile("cp.async.wait_group 0;"); }

// ---------------------------------------------------------------------------
// Split kernels (unchanged)
// ---------------------------------------------------------------------------
__global__ __launch_bounds__(256)
void split_act_all(const float* __restrict__ q, const float* __restrict__ k,
                   const float* __restrict__ v)
{
    const int z = blockIdx.y;
    const float* src = (z == 0) ? q : (z == 1) ? k : v;
    const int i = blockIdx.x * 256 + threadIdx.x;
    float4 val = reinterpret_cast<const float4*>(src)[i];
    __nv_bfloat16 h0, h1, h2, h3, l0, l1, l2, l3;
    split1(val.x, h0, l0); split1(val.y, h1, l1);
    split1(val.z, h2, l2); split1(val.w, h3, l3);
    uint2 hp, lp;
    hp.x = ((uint32_t)__bfloat16_as_ushort(h1) << 16) | __bfloat16_as_ushort(h0);
    hp.y = ((uint32_t)__bfloat16_as_ushort(h3) << 16) | __bfloat16_as_ushort(h2);
    lp.x = ((uint32_t)__bfloat16_as_ushort(l1) << 16) | __bfloat16_as_ushort(l0);
    lp.y = ((uint32_t)__bfloat16_as_ushort(l3) << 16) | __bfloat16_as_ushort(l2);
    reinterpret_cast<uint2*>(g_Ah[z])[i] = hp;
    reinterpret_cast<uint2*>(g_Al[z])[i] = lp;
}

__global__ __launch_bounds__(256)
void split_wt_all(const float* __restrict__ Wq, const float* __restrict__ Wk,
                  const float* __restrict__ Wv, const float* __restrict__ Wo)
{
    __shared__ float tile[32][33];
    const int z = blockIdx.z;
    const float* W = (z == 0) ? Wq : (z == 1) ? Wk : (z == 2) ? Wv : Wo;
    const int tx = threadIdx.x;
    const int ty = threadIdx.y;
    const int n0 = blockIdx.x * 32;
    const int k0 = blockIdx.y * 32;
#pragma unroll
    for (int i = 0; i < 32; i += 8)
        tile[ty + i][tx] = W[(size_t)(k0 + ty + i) * D_ + n0 + tx];
    __syncthreads();
#pragma unroll
    for (int i = 0; i < 32; i += 8) {
        float v = tile[tx][ty + i];
        __nv_bfloat16 h, l;
        split1(v, h, l);
        size_t idx = (size_t)(n0 + ty + i) * D_ + k0 + tx;
        g_Wh[z][idx] = h;
        g_Wl[z][idx] = l;
    }
}

// ---------------------------------------------------------------------------
// Tensor-core GEMM (bf16x3): 256x128 block tile, 512 threads — unchanged R8.
// ---------------------------------------------------------------------------
#define TSTR 40
#define ASZ (256 * TSTR)
#define BSZ (128 * TSTR)
#define STAGE_E (2 * ASZ + 2 * BSZ)

template <int MODE>
__global__ __launch_bounds__(512)
void gemm_tc(const float* __restrict__ bias0, const float* __restrict__ bias1,
             const float* __restrict__ bias2, float* __restrict__ Cout)
{
    extern __shared__ __nv_bfloat16 sm[];

    const int z = (MODE == 1) ? blockIdx.z : 0;
    const __nv_bfloat16* Ah = g_Ah[z];
    const __nv_bfloat16* Al = g_Al[z];
    const __nv_bfloat16* Wh = g_Wh[(MODE == 0) ? 3 : z];
    const __nv_bfloat16* Wl = g_Wl[(MODE == 0) ? 3 : z];
    const float* bias = (MODE == 0) ? bias0 : (z == 0) ? bias0 : (z == 1) ? bias1 : bias2;
    const float oscale = (MODE == 1 && z == 0) ? QSCALE : 1.0f;

    const int tid = threadIdx.x;
    const int bm = blockIdx.y * 256;
    const int bn = blockIdx.x * 128;

    const int lane = tid & 31;
    const int wid  = tid >> 5;
    const int wm   = wid & 7;
    const int wn   = wid >> 3;
    const int g    = lane >> 2;
    const int tg   = lane & 3;

    const int ar   = tid >> 1;
    const int acol = (tid & 1) * 16;
    const int br   = tid >> 2;
    const int bcol = (tid & 3) * 8;

    const uint32_t smb = smem_u32(sm);

    const uint32_t offA = (uint32_t)(((lane & 7) + (((lane >> 3) & 1) * 8)) * TSTR
                                     + (lane >> 4) * 8) * 2;
    const uint32_t offB = (uint32_t)(((lane & 7) + ((lane >> 4) * 8)) * TSTR
                                     + ((lane >> 3) & 1) * 8) * 2;

    auto issue = [&](int kt, int st) {
        const size_t colA = (size_t)kt * 32 + acol;
        const size_t colB = (size_t)kt * 32 + bcol;
        const size_t a0 = (size_t)(bm + ar) * D_ + colA;
        const size_t b0 = (size_t)(bn + br) * D_ + colB;
        const uint32_t base = smb + (uint32_t)st * (STAGE_E * 2);
        const uint32_t sA = base + (uint32_t)(ar * TSTR + acol) * 2;
        const uint32_t sB = base + (uint32_t)(2 * ASZ + br * TSTR + bcol) * 2;
        cpa16(sA,                 Ah + a0);
        cpa16(sA + 16,            Ah + a0 + 8);
        cpa16(sA + ASZ * 2,       Al + a0);
        cpa16(sA + ASZ * 2 + 16,  Al + a0 + 8);
        cpa16(sB,                 Wh + b0);
        cpa16(sB + BSZ * 2,       Wl + b0);
        cp_commit();
    };

    float acc[2][8][4];
#pragma unroll
    for (int mt = 0; mt < 2; mt++)
#pragma unroll
        for (int nt = 0; nt < 8; nt++)
#pragma unroll
            for (int i = 0; i < 4; i++) acc[mt][nt][i] = 0.f;

    issue(0, 0);

    const int NT = D_ / 32;
    for (int kt = 0; kt < NT; kt++) {
        cp_wait0();
        __syncthreads();
        if (kt + 1 < NT) issue(kt + 1, (kt + 1) & 1);

        const uint32_t base = smb + (uint32_t)(kt & 1) * (STAGE_E * 2);
        const uint32_t bAh = base;
        const uint32_t bAl = base + ASZ * 2;
        const uint32_t bBh = base + 2 * ASZ * 2;
        const uint32_t bBl = base + (2 * ASZ + BSZ) * 2;

#pragma unroll
        for (int kk = 0; kk < 32; kk += 16) {
            uint32_t ah[2][4], al[2][4];
#pragma unroll
            for (int mt = 0; mt < 2; mt++) {
                const uint32_t ro = (uint32_t)((wm * 32 + mt * 16) * TSTR + kk) * 2;
                ldsm4(ah[mt], bAh + ro + offA);
                ldsm4(al[mt], bAl + ro + offA);
            }
#pragma unroll
            for (int ntp = 0; ntp < 4; ntp++) {
                const uint32_t ro = (uint32_t)((wn * 64 + ntp * 16) * TSTR + kk) * 2;
                uint32_t bh4[4], bl4[4];
                ldsm4(bh4, bBh + ro + offB);
                ldsm4(bl4, bBl + ro + offB);
                mma16816(acc[0][2 * ntp],     ah[0], &bh4[0]);
                mma16816(acc[1][2 * ntp],     ah[1], &bh4[0]);
                mma16816(acc[0][2 * ntp + 1], ah[0], &bh4[2]);
                mma16816(acc[1][2 * ntp + 1], ah[1], &bh4[2]);
                mma16816(acc[0][2 * ntp],     ah[0], &bl4[0]);
                mma16816(acc[1][2 * ntp],     ah[1], &bl4[0]);
                mma16816(acc[0][2 * ntp + 1], ah[0], &bl4[2]);
                mma16816(acc[1][2 * ntp + 1], ah[1], &bl4[2]);
                mma16816(acc[0][2 * ntp],     al[0], &bh4[0]);
                mma16816(acc[1][2 * ntp],     al[1], &bh4[0]);
                mma16816(acc[0][2 * ntp + 1], al[0], &bh4[2]);
                mma16816(acc[1][2 * ntp + 1], al[1], &bh4[2]);
            }
        }
    }

#pragma unroll
    for (int mt = 0; mt < 2; mt++) {
#pragma unroll
        for (int nt = 0; nt < 8; nt++) {
            const int col = bn + wn * 64 + nt * 8 + tg * 2;
            const float b0 = bias[col], b1 = bias[col + 1];
#pragma unroll
            for (int half = 0; half < 2; half++) {
                const int row = bm + wm * 32 + mt * 16 + g + half * 8;
                float vx = acc[mt][nt][half * 2 + 0] + b0;
                float vy = acc[mt][nt][half * 2 + 1] + b1;
                if (MODE == 0) {
                    *reinterpret_cast<float2*>(Cout + (size_t)row * D_ + col) =
                        make_float2(vx, vy);
                } else {
                    vx *= oscale; vy *= oscale;
                    __nv_bfloat16 hx, lx, hy, ly;
                    split1(vx, hx, lx);
                    split1(vy, hy, ly);
                    const int b  = row >> 11;
                    const int s  = row & (S_ - 1);
                    const int h  = col >> 6;
                    const int dk = col & (DK_ - 1);
                    const size_t bh = (size_t)b * H_ + h;
                    if (z == 0 || z == 1) {
                        const size_t idx = (bh * S_ + s) * DK_ + dk;
                        uint32_t hp = ((uint32_t)__bfloat16_as_ushort(hy) << 16) |
                                      __bfloat16_as_ushort(hx);
                        uint32_t lp = ((uint32_t)__bfloat16_as_ushort(ly) << 16) |
                                      __bfloat16_as_ushort(lx);
                        __nv_bfloat16* dh = (z == 0) ? g_qh : g_kh;
                        __nv_bfloat16* dl = (z == 0) ? g_ql : g_kl;
                        *reinterpret_cast<uint32_t*>(dh + idx) = hp;
                        *reinterpret_cast<uint32_t*>(dl + idx) = lp;
                    } else {
                        const size_t idx = (bh * DK_ + dk) * S_ + s;
                        g_vh[idx]      = hx;
                        g_vh[idx + S_] = hy;
                        g_vl[idx]      = lx;
                        g_vl[idx + S_] = ly;
                    }
                }
            }
        }
    }
}

// ---------------------------------------------------------------------------
// Tensor-core flash attention (bf16x3), fixed-base softmax, KEY-SPLIT warps:
// 8 warps = 4 m-warps x 2 key-halves. Each warp: 16 q-rows x 32 keys.
// Halves LDSM traffic and ex2 count per warp; O partials reduced across the
// key-split pair once at the end (exact reassociation).
// ---------------------------------------------------------------------------
#define KSTR 72
#define ASTAGE (64 * KSTR)

__global__ __launch_bounds__(256, 2)
void attn_tc(const int* __restrict__ mask)
{
    extern __shared__ __nv_bfloat16 sm[];
    float* smadd = reinterpret_cast<float*>(sm + 2 * 4 * ASTAGE);

    const int bh = blockIdx.y;
    const int b  = bh >> 4;
    const int h  = bh & 15;
    const int tid  = threadIdx.x;
    const int lane = tid & 31;
    const int wid  = tid >> 5;
    const int wm   = wid & 3;        // 4 m-warps
    const int wk   = wid >> 2;       // 2 key-halves
    const int g    = lane >> 2;
    const int tg   = lane & 3;
    const int qrow0 = blockIdx.x * 64 + wm * 16;

    const size_t kbase = (size_t)bh * S_ * DK_;
    const size_t vbase = (size_t)bh * DK_ * S_;
    const int lr = tid >> 2;
    const int lc = (tid & 3) * 16;

    const uint32_t smb = smem_u32(sm);
    const uint32_t soff = (uint32_t)(lr * KSTR + lc) * 2;
    const uint32_t offB = (uint32_t)(((lane & 7) + ((lane >> 4) * 8)) * KSTR
                                     + ((lane >> 3) & 1) * 8) * 2;

    auto issue = [&](int kt, int st) {
        const size_t koff = kbase + (size_t)(kt + lr) * DK_ + lc;
        const size_t voff = vbase + (size_t)lr * S_ + kt + lc;
        const uint32_t base = smb + (uint32_t)st * (4 * ASTAGE * 2);
        cpa16(base + soff,                       g_kh + koff);
        cpa16(base + soff + 16,                  g_kh + koff + 8);
        cpa16(base + ASTAGE * 2 + soff,          g_kl + koff);
        cpa16(base + ASTAGE * 2 + soff + 16,     g_kl + koff + 8);
        cpa16(base + 2 * ASTAGE * 2 + soff,      g_vh + voff);
        cpa16(base + 2 * ASTAGE * 2 + soff + 16, g_vh + voff + 8);
        cpa16(base + 3 * ASTAGE * 2 + soff,      g_vl + voff);
        cpa16(base + 3 * ASTAGE * 2 + soff + 16, g_vl + voff + 8);
        cp_commit();
    };

    issue(0, 0);

#pragma unroll
    for (int i = 0; i < S_ / 256; i++)
        smadd[tid + i * 256] = (mask[b * S_ + tid + i * 256] == 0) ? -1e30f : 0.f;

    const size_t qoff = (size_t)bh * S_ * DK_;
    uint32_t aqh[4][4], aql[4][4];
#pragma unroll
    for (int ks = 0; ks < 4; ks++) {
        const int c0 = ks * 16 + 2 * tg;
        const size_t r0 = qoff + (size_t)(qrow0 + g) * DK_;
        const size_t r1 = qoff + (size_t)(qrow0 + g + 8) * DK_;
        aqh[ks][0] = *reinterpret_cast<const uint32_t*>(g_qh + r0 + c0);
        aqh[ks][1] = *reinterpret_cast<const uint32_t*>(g_qh + r1 + c0);
        aqh[ks][2] = *reinterpret_cast<const uint32_t*>(g_qh + r0 + c0 + 8);
        aqh[ks][3] = *reinterpret_cast<const uint32_t*>(g_qh + r1 + c0 + 8);
        aql[ks][0] = *reinterpret_cast<const uint32_t*>(g_ql + r0 + c0);
        aql[ks][1] = *reinterpret_cast<const uint32_t*>(g_ql + r1 + c0);
        aql[ks][2] = *reinterpret_cast<const uint32_t*>(g_ql + r0 + c0 + 8);
        aql[ks][3] = *reinterpret_cast<const uint32_t*>(g_ql + r1 + c0 + 8);
    }

    float accO[8][4];
#pragma unroll
    for (int i = 0; i < 8; i++)
#pragma unroll
        for (int j = 0; j < 4; j++) accO[i][j] = 0.f;

    float sum0 = 0.f, sum1 = 0.f;

    const int NTILES = S_ / 64;
    for (int t = 0; t < NTILES; t++) {
        const int kt = t * 64;
        cp_wait0();
        __syncthreads();
        if (t + 1 < NTILES) issue(kt + 64, (t + 1) & 1);

        const uint32_t bKh = smb + (uint32_t)(t & 1) * (4 * ASTAGE * 2);
        const uint32_t bKl = bKh + ASTAGE * 2;
        const uint32_t bVh = bKh + 2 * ASTAGE * 2;
        const uint32_t bVl = bKh + 3 * ASTAGE * 2;

        // ---- S = Q K^T for this warp's 32-key half ----
        float acc[4][4];
#pragma unroll
        for (int i = 0; i < 4; i++)
#pragma unroll
            for (int j = 0; j < 4; j++) acc[i][j] = 0.f;

#pragma unroll
        for (int ks = 0; ks < 4; ks++)
#pragma unroll
            for (int ntp = 0; ntp < 2; ntp++) {
                const uint32_t ro = (uint32_t)((wk * 32 + ntp * 16) * KSTR + ks * 16) * 2;
                uint32_t kh4[4], kl4[4];
                ldsm4(kh4, bKh + ro + offB);
                ldsm4(kl4, bKl + ro + offB);
                mma16816(acc[2 * ntp],     aqh[ks], &kh4[0]);
                mma16816(acc[2 * ntp + 1], aqh[ks], &kh4[2]);
                mma16816(acc[2 * ntp],     aqh[ks], &kl4[0]);
                mma16816(acc[2 * ntp + 1], aqh[ks], &kl4[2]);
                mma16816(acc[2 * ntp],     aql[ks], &kh4[0]);
                mma16816(acc[2 * ntp + 1], aql[ks], &kh4[2]);
            }

        // ---- p = 2^(s + maskadd); partial row sums; split hi/lo in-place ----
#pragma unroll
        for (int nt = 0; nt < 4; nt++) {
            const float ma = smadd[kt + wk * 32 + nt * 8 + 2 * tg];
            const float mb = smadd[kt + wk * 32 + nt * 8 + 2 * tg + 1];
            const float p0 = fast_exp2(acc[nt][0] + ma);
            const float p1 = fast_exp2(acc[nt][1] + mb);
            const float p2 = fast_exp2(acc[nt][2] + ma);
            const float p3 = fast_exp2(acc[nt][3] + mb);
            sum0 += p0 + p1;
            sum1 += p2 + p3;
            const uint32_t h01 = pack_bf16(p0, p1);
            const uint32_t h23 = pack_bf16(p2, p3);
            const float q0 = p0 - __uint_as_float(h01 << 16);
            const float q1 = p1 - __uint_as_float(h01 & 0xffff0000u);
            const float q2 = p2 - __uint_as_float(h23 << 16);
            const float q3 = p3 - __uint_as_float(h23 & 0xffff0000u);
            const uint32_t l01 = pack_bf16(q0, q1);
            const uint32_t l23 = pack_bf16(q2, q3);
            acc[nt][0] = __uint_as_float(h01);
            acc[nt][1] = __uint_as_float(h23);
            acc[nt][2] = __uint_as_float(l01);
            acc[nt][3] = __uint_as_float(l23);
        }

        // ---- O += P V over this warp's 32 keys ----
#pragma unroll
        for (int kb2 = 0; kb2 < 2; kb2++) {
            uint32_t ph[4], pl[4];
            ph[0] = __float_as_uint(acc[2 * kb2][0]);
            ph[1] = __float_as_uint(acc[2 * kb2][1]);
            ph[2] = __float_as_uint(acc[2 * kb2 + 1][0]);
            ph[3] = __float_as_uint(acc[2 * kb2 + 1][1]);
            pl[0] = __float_as_uint(acc[2 * kb2][2]);
            pl[1] = __float_as_uint(acc[2 * kb2][3]);
            pl[2] = __float_as_uint(acc[2 * kb2 + 1][2]);
            pl[3] = __float_as_uint(acc[2 * kb2 + 1][3]);
#pragma unroll
            for (int ntp = 0; ntp < 4; ntp++) {
                const uint32_t ro = (uint32_t)(ntp * 16 * KSTR + wk * 32 + kb2 * 16) * 2;
                uint32_t vh4[4], vl4[4];
                ldsm4(vh4, bVh + ro + offB);
                ldsm4(vl4, bVl + ro + offB);
                mma16816(accO[2 * ntp],     ph, &vh4[0]);
                mma16816(accO[2 * ntp + 1], ph, &vh4[2]);
                mma16816(accO[2 * ntp],     ph, &vl4[0]);
                mma16816(accO[2 * ntp + 1], ph, &vl4[2]);
                mma16816(accO[2 * ntp],     pl, &vh4[0]);
                mma16816(accO[2 * ntp + 1], pl, &vh4[2]);
            }
        }
    }

    // ---- quad reduce of partial row sums ----
    sum0 += __shfl_xor_sync(0xffffffffu, sum0, 1);
    sum0 += __shfl_xor_sync(0xffffffffu, sum0, 2);
    sum1 += __shfl_xor_sync(0xffffffffu, sum1, 1);
    sum1 += __shfl_xor_sync(0xffffffffu, sum1, 2);

    // ---- cross key-half reduction via smem (stages are dead now) ----
    float* red = reinterpret_cast<float*>(sm);
    const int slot = (wm * 32 + lane) * 34;
    __syncthreads();
    if (wk == 1) {
#pragma unroll
        for (int i = 0; i < 8; i++) {
            red[slot + 4 * i + 0] = accO[i][0];
            red[slot + 4 * i + 1] = accO[i][1];
            red[slot + 4 * i + 2] = accO[i][2];
            red[slot + 4 * i + 3] = accO[i][3];
        }
        red[slot + 32] = sum0;
        red[slot + 33] = sum1;
    }
    __syncthreads();
    if (wk == 0) {
#pragma unroll
        for (int i = 0; i < 8; i++) {
            accO[i][0] += red[slot + 4 * i + 0];
            accO[i][1] += red[slot + 4 * i + 1];
            accO[i][2] += red[slot + 4 * i + 2];
            accO[i][3] += red[slot + 4 * i + 3];
        }
        sum0 += red[slot + 32];
        sum1 += red[slot + 33];

        // ---- epilogue: normalize, split to bf16 hi/lo, write ctx slot 0 ----
        const float i0 = 1.f / sum0;
        const float i1 = 1.f / sum1;
        const size_t orow0 = ((size_t)b * S_ + qrow0 + g) * D_ + h * DK_;
        const size_t orow1 = orow0 + (size_t)8 * D_;
#pragma unroll
        for (int nt2 = 0; nt2 < 8; nt2++) {
            const int dk = nt2 * 8 + 2 * tg;
            float vx0 = accO[nt2][0] * i0, vy0 = accO[nt2][1] * i0;
            float vx1 = accO[nt2][2] * i1, vy1 = accO[nt2][3] * i1;
            __nv_bfloat16 hx, lx, hy, ly;
            split1(vx0, hx, lx); split1(vy0, hy, ly);
            *reinterpret_cast<uint32_t*>(g_Ah[0] + orow0 + dk) =
                ((uint32_t)__bfloat16_as_ushort(hy) << 16) | __bfloat16_as_ushort(hx);
            *reinterpret_cast<uint32_t*>(g_Al[0] + orow0 + dk) =
                ((uint32_t)__bfloat16_as_ushort(ly) << 16) | __bfloat16_as_ushort(lx);
            split1(vx1, hx, lx); split1(vy1, hy, ly);
            *reinterpret_cast<uint32_t*>(g_Ah[0] + orow1 + dk) =
                ((uint32_t)__bfloat16_as_ushort(hy) << 16) | __bfloat16_as_ushort(hx);
            *reinterpret_cast<uint32_t*>(g_Al[0] + orow1 + dk) =
                ((uint32_t)__bfloat16_as_ushort(ly) << 16) | __bfloat16_as_ushort(lx);
        }
    }
}

// ---------------------------------------------------------------------------
// Launch
// ---------------------------------------------------------------------------
#define GEMM_SMEM (2 * STAGE_E * 2)
#define ATTN_SMEM (2 * 4 * ASTAGE * 2 + S_ * 4)

extern "C" void kernel_launch(void* const* d_in, const int* in_sizes, int n_in,
                              void* d_out, int out_size)
{
    const float* query = (const float*)d_in[0];
    const float* key   = (const float*)d_in[1];
    const float* value = (const float*)d_in[2];
    const int*   mask  = (const int*)  d_in[3];
    const float* Wq = (const float*)d_in[4];
    const float* bq = (const float*)d_in[5];
    const float* Wk = (const float*)d_in[6];
    const float* bk = (const float*)d_in[7];
    const float* Wv = (const float*)d_in[8];
    const float* bv = (const float*)d_in[9];
    const float* Wo = (const float*)d_in[10];
    const float* bo = (const float*)d_in[11];
    float* out = (float*)d_out;

    cudaFuncSetAttribute(gemm_tc<1>, cudaFuncAttributeMaxDynamicSharedMemorySize, GEMM_SMEM);
    cudaFuncSetAttribute(gemm_tc<0>, cudaFuncAttributeMaxDynamicSharedMemorySize, GEMM_SMEM);
    cudaFuncSetAttribute(attn_tc,    cudaFuncAttributeMaxDynamicSharedMemorySize, ATTN_SMEM);

    dim3 wtg(D_ / 32, D_ / 32, 4);
    split_wt_all<<<wtg, dim3(32, 8)>>>(Wq, Wk, Wv, Wo);
    dim3 sag((M_ * D_ / 4) / 256, 3);
    split_act_all<<<sag, 256>>>(query, key, value);

    dim3 gqkv(D_ / 128, M_ / 256, 3);
    gemm_tc<1><<<gqkv, 512, GEMM_SMEM>>>(bq, bk, bv, nullptr);

    dim3 agrid(S_ / 64, B_ * H_);     // (32, 32): 64 q-rows per CTA
    attn_tc<<<agrid, 256, ATTN_SMEM>>>(mask);

    dim3 gout(D_ / 128, M_ / 256);
    gemm_tc<0><<<gout, 512, GEMM_SMEM>>>(bo, nullptr, nullptr, out);
}

// round 12
// speedup vs baseline: 1.0069x; 1.0069x over previous
#include <cuda_runtime.h>
#include <cuda_bf16.h>
#include <stdint.h>

// Problem constants
#define B_  2
#define S_  2048
#define D_  1024
#define H_  16
#define DK_ 64
#define M_  (B_ * S_)

#define QSCALE (0.125f * 1.44269504088896340736f)

// ---------------------------------------------------------------------------
// Scratch (device globals — no allocations allowed)
// ---------------------------------------------------------------------------
__device__ __nv_bfloat16 g_Ah[3][M_ * D_];   // activation hi (slot 0 reused for ctx)
__device__ __nv_bfloat16 g_Al[3][M_ * D_];   // activation lo
__device__ __nv_bfloat16 g_Wh[4][D_ * D_];   // weight hi, TRANSPOSED [N][K]
__device__ __nv_bfloat16 g_Wl[4][D_ * D_];   // weight lo

__device__ __nv_bfloat16 g_qh[B_ * H_ * S_ * DK_];  // [bh][s][dk], pre-scaled
__device__ __nv_bfloat16 g_ql[B_ * H_ * S_ * DK_];
__device__ __nv_bfloat16 g_kh[B_ * H_ * S_ * DK_];
__device__ __nv_bfloat16 g_kl[B_ * H_ * S_ * DK_];
__device__ __nv_bfloat16 g_vh[B_ * H_ * DK_ * S_];  // TRANSPOSED [bh][dk][s]
__device__ __nv_bfloat16 g_vl[B_ * H_ * DK_ * S_];

// ---------------------------------------------------------------------------
// Helpers
// ---------------------------------------------------------------------------
__device__ __forceinline__ void split1(float x, __nv_bfloat16& h, __nv_bfloat16& l) {
    h = __float2bfloat16_rn(x);
    l = __float2bfloat16_rn(x - __bfloat162float(h));
}

__device__ __forceinline__ uint32_t pack_bf16(float lo, float hi) {
    uint32_t r;
    asm("cvt.rn.bf16x2.f32 %0, %1, %2;" : "=r"(r) : "f"(hi), "f"(lo));
    return r;
}

__device__ __forceinline__ float fast_exp2(float x) {
    float r;
    asm("ex2.approx.f32 %0, %1;" : "=f"(r) : "f"(x));
    return r;
}

__device__ __forceinline__ void mma16816(float* c, const uint32_t* a, const uint32_t* b)
{
    asm("mma.sync.aligned.m16n8k16.row.col.f32.bf16.bf16.f32 "
        "{%0,%1,%2,%3},{%4,%5,%6,%7},{%8,%9},{%0,%1,%2,%3};"
        : "+f"(c[0]), "+f"(c[1]), "+f"(c[2]), "+f"(c[3])
        : "r"(a[0]), "r"(a[1]), "r"(a[2]), "r"(a[3]), "r"(b[0]), "r"(b[1]));
}

__device__ __forceinline__ void ldsm4(uint32_t* r, uint32_t addr)
{
    asm volatile("ldmatrix.sync.aligned.m8n8.x4.shared.b16 {%0,%1,%2,%3}, [%4];"
        : "=r"(r[0]), "=r"(r[1]), "=r"(r[2]), "=r"(r[3]) : "r"(addr));
}

__device__ __forceinline__ uint32_t smem_u32(const void* p) {
    return (uint32_t)__cvta_generic_to_shared(p);
}
__device__ __forceinline__ void cpa16(uint32_t d, const void* s) {
    asm volatile("cp.async.cg.shared.global [%0], [%1], 16;" :: "r"(d), "l"(s));
}
__device__ __forceinline__ void cp_commit() { asm volatile("cp.async.commit_group;"); }
__device__ __forceinline__ void cp_wait0()  { asm volatile("cp.async.wait_group 0;"); }

// ---------------------------------------------------------------------------
// Split kernels (unchanged)
// ---------------------------------------------------------------------------
__global__ __launch_bounds__(256)
void split_act_all(const float* __restrict__ q, const float* __restrict__ k,
                   const float* __restrict__ v)
{
    const int z = blockIdx.y;
    const float* src = (z == 0) ? q : (z == 1) ? k : v;
    const int i = blockIdx.x * 256 + threadIdx.x;
    float4 val = reinterpret_cast<const float4*>(src)[i];
    __nv_bfloat16 h0, h1, h2, h3, l0, l1, l2, l3;
    split1(val.x, h0, l0); split1(val.y, h1, l1);
    split1(val.z, h2, l2); split1(val.w, h3, l3);
    uint2 hp, lp;
    hp.x = ((uint32_t)__bfloat16_as_ushort(h1) << 16) | __bfloat16_as_ushort(h0);
    hp.y = ((uint32_t)__bfloat16_as_ushort(h3) << 16) | __bfloat16_as_ushort(h2);
    lp.x = ((uint32_t)__bfloat16_as_ushort(l1) << 16) | __bfloat16_as_ushort(l0);
    lp.y = ((uint32_t)__bfloat16_as_ushort(l3) << 16) | __bfloat16_as_ushort(l2);
    reinterpret_cast<uint2*>(g_Ah[z])[i] = hp;
    reinterpret_cast<uint2*>(g_Al[z])[i] = lp;
}

__global__ __launch_bounds__(256)
void split_wt_all(const float* __restrict__ Wq, const float* __restrict__ Wk,
                  const float* __restrict__ Wv, const float* __restrict__ Wo)
{
    __shared__ float tile[32][33];
    const int z = blockIdx.z;
    const float* W = (z == 0) ? Wq : (z == 1) ? Wk : (z == 2) ? Wv : Wo;
    const int tx = threadIdx.x;
    const int ty = threadIdx.y;
    const int n0 = blockIdx.x * 32;
    const int k0 = blockIdx.y * 32;
#pragma unroll
    for (int i = 0; i < 32; i += 8)
        tile[ty + i][tx] = W[(size_t)(k0 + ty + i) * D_ + n0 + tx];
    __syncthreads();
#pragma unroll
    for (int i = 0; i < 32; i += 8) {
        float v = tile[tx][ty + i];
        __nv_bfloat16 h, l;
        split1(v, h, l);
        size_t idx = (size_t)(n0 + ty + i) * D_ + k0 + tx;
        g_Wh[z][idx] = h;
        g_Wl[z][idx] = l;
    }
}

// ---------------------------------------------------------------------------
// Tensor-core GEMM (bf16x3): 256x128 block tile, 512 threads — unchanged R8.
// ---------------------------------------------------------------------------
#define TSTR 40
#define ASZ (256 * TSTR)
#define BSZ (128 * TSTR)
#define STAGE_E (2 * ASZ + 2 * BSZ)

template <int MODE>
__global__ __launch_bounds__(512)
void gemm_tc(const float* __restrict__ bias0, const float* __restrict__ bias1,
             const float* __restrict__ bias2, float* __restrict__ Cout)
{
    extern __shared__ __nv_bfloat16 sm[];

    const int z = (MODE == 1) ? blockIdx.z : 0;
    const __nv_bfloat16* Ah = g_Ah[z];
    const __nv_bfloat16* Al = g_Al[z];
    const __nv_bfloat16* Wh = g_Wh[(MODE == 0) ? 3 : z];
    const __nv_bfloat16* Wl = g_Wl[(MODE == 0) ? 3 : z];
    const float* bias = (MODE == 0) ? bias0 : (z == 0) ? bias0 : (z == 1) ? bias1 : bias2;
    const float oscale = (MODE == 1 && z == 0) ? QSCALE : 1.0f;

    const int tid = threadIdx.x;
    const int bm = blockIdx.y * 256;
    const int bn = blockIdx.x * 128;

    const int lane = tid & 31;
    const int wid  = tid >> 5;
    const int wm   = wid & 7;
    const int wn   = wid >> 3;
    const int g    = lane >> 2;
    const int tg   = lane & 3;

    const int ar   = tid >> 1;
    const int acol = (tid & 1) * 16;
    const int br   = tid >> 2;
    const int bcol = (tid & 3) * 8;

    const uint32_t smb = smem_u32(sm);

    const uint32_t offA = (uint32_t)(((lane & 7) + (((lane >> 3) & 1) * 8)) * TSTR
                                     + (lane >> 4) * 8) * 2;
    const uint32_t offB = (uint32_t)(((lane & 7) + ((lane >> 4) * 8)) * TSTR
                                     + ((lane >> 3) & 1) * 8) * 2;

    auto issue = [&](int kt, int st) {
        const size_t colA = (size_t)kt * 32 + acol;
        const size_t colB = (size_t)kt * 32 + bcol;
        const size_t a0 = (size_t)(bm + ar) * D_ + colA;
        const size_t b0 = (size_t)(bn + br) * D_ + colB;
        const uint32_t base = smb + (uint32_t)st * (STAGE_E * 2);
        const uint32_t sA = base + (uint32_t)(ar * TSTR + acol) * 2;
        const uint32_t sB = base + (uint32_t)(2 * ASZ + br * TSTR + bcol) * 2;
        cpa16(sA,                 Ah + a0);
        cpa16(sA + 16,            Ah + a0 + 8);
        cpa16(sA + ASZ * 2,       Al + a0);
        cpa16(sA + ASZ * 2 + 16,  Al + a0 + 8);
        cpa16(sB,                 Wh + b0);
        cpa16(sB + BSZ * 2,       Wl + b0);
        cp_commit();
    };

    float acc[2][8][4];
#pragma unroll
    for (int mt = 0; mt < 2; mt++)
#pragma unroll
        for (int nt = 0; nt < 8; nt++)
#pragma unroll
            for (int i = 0; i < 4; i++) acc[mt][nt][i] = 0.f;

    issue(0, 0);

    const int NT = D_ / 32;
    for (int kt = 0; kt < NT; kt++) {
        cp_wait0();
        __syncthreads();
        if (kt + 1 < NT) issue(kt + 1, (kt + 1) & 1);

        const uint32_t base = smb + (uint32_t)(kt & 1) * (STAGE_E * 2);
        const uint32_t bAh = base;
        const uint32_t bAl = base + ASZ * 2;
        const uint32_t bBh = base + 2 * ASZ * 2;
        const uint32_t bBl = base + (2 * ASZ + BSZ) * 2;

#pragma unroll
        for (int kk = 0; kk < 32; kk += 16) {
            uint32_t ah[2][4], al[2][4];
#pragma unroll
            for (int mt = 0; mt < 2; mt++) {
                const uint32_t ro = (uint32_t)((wm * 32 + mt * 16) * TSTR + kk) * 2;
                ldsm4(ah[mt], bAh + ro + offA);
                ldsm4(al[mt], bAl + ro + offA);
            }
#pragma unroll
            for (int ntp = 0; ntp < 4; ntp++) {
                const uint32_t ro = (uint32_t)((wn * 64 + ntp * 16) * TSTR + kk) * 2;
                uint32_t bh4[4], bl4[4];
                ldsm4(bh4, bBh + ro + offB);
                ldsm4(bl4, bBl + ro + offB);
                mma16816(acc[0][2 * ntp],     ah[0], &bh4[0]);
                mma16816(acc[1][2 * ntp],     ah[1], &bh4[0]);
                mma16816(acc[0][2 * ntp + 1], ah[0], &bh4[2]);
                mma16816(acc[1][2 * ntp + 1], ah[1], &bh4[2]);
                mma16816(acc[0][2 * ntp],     ah[0], &bl4[0]);
                mma16816(acc[1][2 * ntp],     ah[1], &bl4[0]);
                mma16816(acc[0][2 * ntp + 1], ah[0], &bl4[2]);
                mma16816(acc[1][2 * ntp + 1], ah[1], &bl4[2]);
                mma16816(acc[0][2 * ntp],     al[0], &bh4[0]);
                mma16816(acc[1][2 * ntp],     al[1], &bh4[0]);
                mma16816(acc[0][2 * ntp + 1], al[0], &bh4[2]);
                mma16816(acc[1][2 * ntp + 1], al[1], &bh4[2]);
            }
        }
    }

#pragma unroll
    for (int mt = 0; mt < 2; mt++) {
#pragma unroll
        for (int nt = 0; nt < 8; nt++) {
            const int col = bn + wn * 64 + nt * 8 + tg * 2;
            const float b0 = bias[col], b1 = bias[col + 1];
#pragma unroll
            for (int half = 0; half < 2; half++) {
                const int row = bm + wm * 32 + mt * 16 + g + half * 8;
                float vx = acc[mt][nt][half * 2 + 0] + b0;
                float vy = acc[mt][nt][half * 2 + 1] + b1;
                if (MODE == 0) {
                    *reinterpret_cast<float2*>(Cout + (size_t)row * D_ + col) =
                        make_float2(vx, vy);
                } else {
                    vx *= oscale; vy *= oscale;
                    __nv_bfloat16 hx, lx, hy, ly;
                    split1(vx, hx, lx);
                    split1(vy, hy, ly);
                    const int b  = row >> 11;
                    const int s  = row & (S_ - 1);
                    const int h  = col >> 6;
                    const int dk = col & (DK_ - 1);
                    const size_t bh = (size_t)b * H_ + h;
                    if (z == 0 || z == 1) {
                        const size_t idx = (bh * S_ + s) * DK_ + dk;
                        uint32_t hp = ((uint32_t)__bfloat16_as_ushort(hy) << 16) |
                                      __bfloat16_as_ushort(hx);
                        uint32_t lp = ((uint32_t)__bfloat16_as_ushort(ly) << 16) |
                                      __bfloat16_as_ushort(lx);
                        __nv_bfloat16* dh = (z == 0) ? g_qh : g_kh;
                        __nv_bfloat16* dl = (z == 0) ? g_ql : g_kl;
                        *reinterpret_cast<uint32_t*>(dh + idx) = hp;
                        *reinterpret_cast<uint32_t*>(dl + idx) = lp;
                    } else {
                        const size_t idx = (bh * DK_ + dk) * S_ + s;
                        g_vh[idx]      = hx;
                        g_vh[idx + S_] = hy;
                        g_vl[idx]      = lx;
                        g_vl[idx + S_] = ly;
                    }
                }
            }
        }
    }
}

// ---------------------------------------------------------------------------
// Tensor-core flash attention (bf16x3), fixed-base softmax, softmax fused
// into the PV loop at 16-key group granularity. Packing order identical to
// the passing R8 kernel: ph = {h01_even, h23_even, h01_odd, h23_odd}.
// ---------------------------------------------------------------------------
#define KSTR 72
#define ASTAGE (64 * KSTR)

__global__ __launch_bounds__(256, 2)
void attn_tc(const int* __restrict__ mask)
{
    extern __shared__ __nv_bfloat16 sm[];
    float* smadd = reinterpret_cast<float*>(sm + 2 * 4 * ASTAGE);

    const int bh = blockIdx.y;
    const int b  = bh >> 4;
    const int h  = bh & 15;
    const int tid  = threadIdx.x;
    const int lane = tid & 31;
    const int wid  = tid >> 5;
    const int g    = lane >> 2;
    const int tg   = lane & 3;
    const int qrow0 = blockIdx.x * 128 + wid * 16;

    const size_t kbase = (size_t)bh * S_ * DK_;
    const size_t vbase = (size_t)bh * DK_ * S_;
    const int lr = tid >> 2;
    const int lc = (tid & 3) * 16;

    const uint32_t smb = smem_u32(sm);
    const uint32_t soff = (uint32_t)(lr * KSTR + lc) * 2;
    const uint32_t offB = (uint32_t)(((lane & 7) + ((lane >> 4) * 8)) * KSTR
                                     + ((lane >> 3) & 1) * 8) * 2;

    auto issue = [&](int kt, int st) {
        const size_t koff = kbase + (size_t)(kt + lr) * DK_ + lc;
        const size_t voff = vbase + (size_t)lr * S_ + kt + lc;
        const uint32_t base = smb + (uint32_t)st * (4 * ASTAGE * 2);
        cpa16(base + soff,                       g_kh + koff);
        cpa16(base + soff + 16,                  g_kh + koff + 8);
        cpa16(base + ASTAGE * 2 + soff,          g_kl + koff);
        cpa16(base + ASTAGE * 2 + soff + 16,     g_kl + koff + 8);
        cpa16(base + 2 * ASTAGE * 2 + soff,      g_vh + voff);
        cpa16(base + 2 * ASTAGE * 2 + soff + 16, g_vh + voff + 8);
        cpa16(base + 3 * ASTAGE * 2 + soff,      g_vl + voff);
        cpa16(base + 3 * ASTAGE * 2 + soff + 16, g_vl + voff + 8);
        cp_commit();
    };

    issue(0, 0);

#pragma unroll
    for (int i = 0; i < S_ / 256; i++)
        smadd[tid + i * 256] = (mask[b * S_ + tid + i * 256] == 0) ? -1e30f : 0.f;

    const size_t qoff = (size_t)bh * S_ * DK_;
    uint32_t aqh[4][4], aql[4][4];
#pragma unroll
    for (int ks = 0; ks < 4; ks++) {
        const int c0 = ks * 16 + 2 * tg;
        const size_t r0 = qoff + (size_t)(qrow0 + g) * DK_;
        const size_t r1 = qoff + (size_t)(qrow0 + g + 8) * DK_;
        aqh[ks][0] = *reinterpret_cast<const uint32_t*>(g_qh + r0 + c0);
        aqh[ks][1] = *reinterpret_cast<const uint32_t*>(g_qh + r1 + c0);
        aqh[ks][2] = *reinterpret_cast<const uint32_t*>(g_qh + r0 + c0 + 8);
        aqh[ks][3] = *reinterpret_cast<const uint32_t*>(g_qh + r1 + c0 + 8);
        aql[ks][0] = *reinterpret_cast<const uint32_t*>(g_ql + r0 + c0);
        aql[ks][1] = *reinterpret_cast<const uint32_t*>(g_ql + r1 + c0);
        aql[ks][2] = *reinterpret_cast<const uint32_t*>(g_ql + r0 + c0 + 8);
        aql[ks][3] = *reinterpret_cast<const uint32_t*>(g_ql + r1 + c0 + 8);
    }

    float accO[8][4];
#pragma unroll
    for (int i = 0; i < 8; i++)
#pragma unroll
        for (int j = 0; j < 4; j++) accO[i][j] = 0.f;

    float sum0 = 0.f, sum1 = 0.f;

    const int NTILES = S_ / 64;
    for (int t = 0; t < NTILES; t++) {
        const int kt = t * 64;
        cp_wait0();
        __syncthreads();
        if (t + 1 < NTILES) issue(kt + 64, (t + 1) & 1);

        const uint32_t bKh = smb + (uint32_t)(t & 1) * (4 * ASTAGE * 2);
        const uint32_t bKl = bKh + ASTAGE * 2;
        const uint32_t bVh = bKh + 2 * ASTAGE * 2;
        const uint32_t bVl = bKh + 3 * ASTAGE * 2;

        // ---- S = Q K^T (pure tensor phase) ----
        float acc[8][4];
#pragma unroll
        for (int i = 0; i < 8; i++)
#pragma unroll
            for (int j = 0; j < 4; j++) acc[i][j] = 0.f;

#pragma unroll
        for (int ks = 0; ks < 4; ks++)
#pragma unroll
            for (int ntp = 0; ntp < 4; ntp++) {
                const uint32_t ro = (uint32_t)(ntp * 16 * KSTR + ks * 16) * 2;
                uint32_t kh4[4], kl4[4];
                ldsm4(kh4, bKh + ro + offB);
                ldsm4(kl4, bKl + ro + offB);
                mma16816(acc[2 * ntp],     aqh[ks], &kh4[0]);
                mma16816(acc[2 * ntp + 1], aqh[ks], &kh4[2]);
                mma16816(acc[2 * ntp],     aqh[ks], &kl4[0]);
                mma16816(acc[2 * ntp + 1], aqh[ks], &kl4[2]);
                mma16816(acc[2 * ntp],     aql[ks], &kh4[0]);
                mma16816(acc[2 * ntp + 1], aql[ks], &kh4[2]);
            }

        // ---- fused per-group softmax + PV (R8 packing order, no swap) ----
#pragma unroll
        for (int kb2 = 0; kb2 < 4; kb2++) {
            uint32_t ph[4], pl[4];
#pragma unroll
            for (int half = 0; half < 2; half++) {
                const int nt = 2 * kb2 + half;
                const float ma = smadd[kt + nt * 8 + 2 * tg];
                const float mb = smadd[kt + nt * 8 + 2 * tg + 1];
                const float p0 = fast_exp2(acc[nt][0] + ma);
                const float p1 = fast_exp2(acc[nt][1] + mb);
                const float p2 = fast_exp2(acc[nt][2] + ma);
                const float p3 = fast_exp2(acc[nt][3] + mb);
                sum0 += p0 + p1;
                sum1 += p2 + p3;
                const uint32_t h01 = pack_bf16(p0, p1);
                const uint32_t h23 = pack_bf16(p2, p3);
                const float q0 = p0 - __uint_as_float(h01 << 16);
                const float q1 = p1 - __uint_as_float(h01 & 0xffff0000u);
                const float q2 = p2 - __uint_as_float(h23 << 16);
                const float q3 = p3 - __uint_as_float(h23 & 0xffff0000u);
                ph[2 * half + 0] = h01;
                ph[2 * half + 1] = h23;
                pl[2 * half + 0] = pack_bf16(q0, q1);
                pl[2 * half + 1] = pack_bf16(q2, q3);
            }
            // ph = {h01_even, h23_even, h01_odd, h23_odd} — identical to R8.
#pragma unroll
            for (int ntp = 0; ntp < 4; ntp++) {
                const uint32_t ro = (uint32_t)(ntp * 16 * KSTR + kb2 * 16) * 2;
                uint32_t vh4[4], vl4[4];
                ldsm4(vh4, bVh + ro + offB);
                ldsm4(vl4, bVl + ro + offB);
                mma16816(accO[2 * ntp],     ph, &vh4[0]);
                mma16816(accO[2 * ntp + 1], ph, &vh4[2]);
                mma16816(accO[2 * ntp],     ph, &vl4[0]);
                mma16816(accO[2 * ntp + 1], ph, &vl4[2]);
                mma16816(accO[2 * ntp],     pl, &vh4[0]);
                mma16816(accO[2 * ntp + 1], pl, &vh4[2]);
            }
        }
    }

    sum0 += __shfl_xor_sync(0xffffffffu, sum0, 1);
    sum0 += __shfl_xor_sync(0xffffffffu, sum0, 2);
    sum1 += __shfl_xor_sync(0xffffffffu, sum1, 1);
    sum1 += __shfl_xor_sync(0xffffffffu, sum1, 2);

    const float i0 = 1.f / sum0;
    const float i1 = 1.f / sum1;
    const size_t orow0 = ((size_t)b * S_ + qrow0 + g) * D_ + h * DK_;
    const size_t orow1 = orow0 + (size_t)8 * D_;
#pragma unroll
    for (int nt2 = 0; nt2 < 8; nt2++) {
        const int dk = nt2 * 8 + 2 * tg;
        float vx0 = accO[nt2][0] * i0, vy0 = accO[nt2][1] * i0;
        float vx1 = accO[nt2][2] * i1, vy1 = accO[nt2][3] * i1;
        __nv_bfloat16 hx, lx, hy, ly;
        split1(vx0, hx, lx); split1(vy0, hy, ly);
        *reinterpret_cast<uint32_t*>(g_Ah[0] + orow0 + dk) =
            ((uint32_t)__bfloat16_as_ushort(hy) << 16) | __bfloat16_as_ushort(hx);
        *reinterpret_cast<uint32_t*>(g_Al[0] + orow0 + dk) =
            ((uint32_t)__bfloat16_as_ushort(ly) << 16) | __bfloat16_as_ushort(lx);
        split1(vx1, hx, lx); split1(vy1, hy, ly);
        *reinterpret_cast<uint32_t*>(g_Ah[0] + orow1 + dk) =
            ((uint32_t)__bfloat16_as_ushort(hy) << 16) | __bfloat16_as_ushort(hx);
        *reinterpret_cast<uint32_t*>(g_Al[0] + orow1 + dk) =
            ((uint32_t)__bfloat16_as_ushort(ly) << 16) | __bfloat16_as_ushort(lx);
    }
}

// ---------------------------------------------------------------------------
// Launch
// ---------------------------------------------------------------------------
#define GEMM_SMEM (2 * STAGE_E * 2)
#define ATTN_SMEM (2 * 4 * ASTAGE * 2 + S_ * 4)

extern "C" void kernel_launch(void* const* d_in, const int* in_sizes, int n_in,
                              void* d_out, int out_size)
{
    const float* query = (const float*)d_in[0];
    const float* key   = (const float*)d_in[1];
    const float* value = (const float*)d_in[2];
    const int*   mask  = (const int*)  d_in[3];
    const float* Wq = (const float*)d_in[4];
    const float* bq = (const float*)d_in[5];
    const float* Wk = (const float*)d_in[6];
    const float* bk = (const float*)d_in[7];
    const float* Wv = (const float*)d_in[8];
    const float* bv = (const float*)d_in[9];
    const float* Wo = (const float*)d_in[10];
    const float* bo = (const float*)d_in[11];
    float* out = (float*)d_out;

    cudaFuncSetAttribute(gemm_tc<1>, cudaFuncAttributeMaxDynamicSharedMemorySize, GEMM_SMEM);
    cudaFuncSetAttribute(gemm_tc<0>, cudaFuncAttributeMaxDynamicSharedMemorySize, GEMM_SMEM);
    cudaFuncSetAttribute(attn_tc,    cudaFuncAttributeMaxDynamicSharedMemorySize, ATTN_SMEM);

    dim3 wtg(D_ / 32, D_ / 32, 4);
    split_wt_all<<<wtg, dim3(32, 8)>>>(Wq, Wk, Wv, Wo);
    dim3 sag((M_ * D_ / 4) / 256, 3);
    split_act_all<<<sag, 256>>>(query, key, value);

    dim3 gqkv(D_ / 128, M_ / 256, 3);
    gemm_tc<1><<<gqkv, 512, GEMM_SMEM>>>(bq, bk, bv, nullptr);

    dim3 agrid(S_ / 128, B_ * H_);
    attn_tc<<<agrid, 256, ATTN_SMEM>>>(mask);

    dim3 gout(D_ / 128, M_ / 256);
    gemm_tc<0><<<gout, 512, GEMM_SMEM>>>(bo, nullptr, nullptr, out);
}